// round 2
// baseline (speedup 1.0000x reference)
#include <cuda_runtime.h>

// Problem constants
constexpr int BATCH = 128;
constexpr int TSEQ  = 512;
constexpr int KIN   = 906;
constexpr int NG    = 16;     // 4*H gates
constexpr int KHALF = 453;    // K split point
constexpr int NCH   = 15;     // chunks of 32 per half (14*32 + 5)
constexpr int RPB   = 256;    // rows per block
constexpr int PITCH = 258;    // smem x-tile pitch (floats): even (LDS.64 align), 2-way STS ok

// Scratch (device globals; no allocation allowed)
__device__ __align__(16) float g_xp0[BATCH * TSEQ * NG];  // K-half 0 partial (permuted [b][t][j][ifgo], i/f/o pre-scaled 0.5, bias folded)
__device__ __align__(16) float g_xp1[BATCH * TSEQ * NG];  // K-half 1 partial
__device__ float g_hf[BATCH * 4];

// ---------- packed fp32x2 helpers (Blackwell FFMA2) ----------
__device__ __forceinline__ unsigned long long pack2(float x) {
    unsigned long long r;
    asm("mov.b64 %0, {%1, %1};" : "=l"(r) : "f"(x));
    return r;
}
__device__ __forceinline__ unsigned long long fma2(unsigned long long a,
                                                   unsigned long long b,
                                                   unsigned long long c) {
    unsigned long long d;
    asm("fma.rn.f32x2 %0, %1, %2, %3;" : "=l"(d) : "l"(a), "l"(b), "l"(c));
    return d;
}
__device__ __forceinline__ void unpack2(unsigned long long a, float& lo, float& hi) {
    asm("mov.b64 {%0, %1}, %2;" : "=f"(lo), "=f"(hi) : "l"(a));
}

// ---------- activations ----------
__device__ __forceinline__ float tanha(float x) {   // MUFU.TANH, 16 cyc
    float r;
    asm("tanh.approx.f32 %0, %1;" : "=f"(r) : "f"(x));
    return r;
}
__device__ __forceinline__ float sigmoid_acc(float x) {  // accurate (tail only)
    float e = __expf(-x);
    return __fdividef(1.0f, 1.0f + e);
}
__device__ __forceinline__ float tanh_acc(float x) {     // accurate (tail only)
    float e = __expf(2.0f * x);
    return 1.0f - __fdividef(2.0f, 1.0f + e);
}

// ---------- cp.async 4B ----------
__device__ __forceinline__ void cp4(float* dst, const float* src) {
    unsigned d = (unsigned)__cvta_generic_to_shared(dst);
    asm volatile("cp.async.ca.shared.global [%0], [%1], 4;" :: "r"(d), "l"(src));
}
__device__ __forceinline__ void cp_commit() { asm volatile("cp.async.commit_group;"); }
__device__ __forceinline__ void cp_wait1()  { asm volatile("cp.async.wait_group 1;" ::: "memory"); }

// =====================================================================
// Kernel 1: projection (2-way K-split partial sums).
// Block: 128 threads, 256 rows (R=2 rows/thread), grid (256, 2).
// SMEM: double-buffered k-major x tile sxT[2][32][PITCH] + W tile sw[2][32][16].
// i/f/o gate outputs pre-scaled by 0.5 (sigmoid-via-tanh folding).
// =====================================================================
__global__ __launch_bounds__(128) void proj_kernel(const float* __restrict__ x,
                                                   const float* __restrict__ Wih,
                                                   const float* __restrict__ bih,
                                                   const float* __restrict__ bhh) {
    extern __shared__ float smem[];
    float* const sxb[2] = { smem, smem + 32 * PITCH };
    float* const swb[2] = { smem + 2 * 32 * PITCH, smem + 2 * 32 * PITCH + 512 };

    const int tid  = threadIdx.x;
    const int lane = tid & 31;
    const int rg   = tid >> 5;                  // row-group 0..3
    const int half = blockIdx.y;
    const int kb   = half * KHALF;
    const size_t row0 = (size_t)blockIdx.x * RPB;

    unsigned long long accA[8], accB[8];
#pragma unroll
    for (int m = 0; m < 8; ++m) { accA[m] = 0ull; accB[m] = 0ull; }

    // ---- async chunk loader: x[row0+r][k0+kk] -> sxT[kk][r], W -> sw[kk][g] ----
    auto issue_chunk = [&](int ch) {
        if (ch >= NCH) return;
        const int k0 = kb + ch * 32;
        const int w  = (ch == NCH - 1) ? (KHALF - 32 * (NCH - 1)) : 32;  // 32 or 5
        if (lane < w) {
            float* sx = sxb[ch & 1];
            float* sw = swb[ch & 1];
            const float* xs = x + (row0 + rg) * KIN + k0 + lane;
            float* xd = sx + lane * PITCH + rg;
#pragma unroll
            for (int i = 0; i < 64; ++i)
                cp4(xd + 4 * i, xs + (size_t)4 * i * KIN);
#pragma unroll
            for (int jj = 0; jj < 4; ++jj) {
                const int g = rg + 4 * jj;
                cp4(sw + lane * 16 + g, Wih + (size_t)g * KIN + k0 + lane);
            }
        }
    };

#define PROJ_K(SX, SW, KK)                                                    \
    {                                                                         \
        const float2 xv = *(const float2*)((SX) + (KK) * PITCH + 2 * tid);    \
        const unsigned long long xa = pack2(xv.x);                            \
        const unsigned long long xb = pack2(xv.y);                            \
        const ulonglong2* wr = (const ulonglong2*)((SW) + (KK) * 16);         \
        ulonglong2 w0 = wr[0], w1 = wr[1];                                    \
        accA[0] = fma2(xa, w0.x, accA[0]);  accB[0] = fma2(xb, w0.x, accB[0]);\
        accA[1] = fma2(xa, w0.y, accA[1]);  accB[1] = fma2(xb, w0.y, accB[1]);\
        accA[2] = fma2(xa, w1.x, accA[2]);  accB[2] = fma2(xb, w1.x, accB[2]);\
        accA[3] = fma2(xa, w1.y, accA[3]);  accB[3] = fma2(xb, w1.y, accB[3]);\
        ulonglong2 w2 = wr[2], w3 = wr[3];                                    \
        accA[4] = fma2(xa, w2.x, accA[4]);  accB[4] = fma2(xb, w2.x, accB[4]);\
        accA[5] = fma2(xa, w2.y, accA[5]);  accB[5] = fma2(xb, w2.y, accB[5]);\
        accA[6] = fma2(xa, w3.x, accA[6]);  accB[6] = fma2(xb, w3.x, accB[6]);\
        accA[7] = fma2(xa, w3.y, accA[7]);  accB[7] = fma2(xb, w3.y, accB[7]);\
    }

    issue_chunk(0); cp_commit();
    issue_chunk(1); cp_commit();

    for (int ch = 0; ch < NCH; ++ch) {
        cp_wait1();
        __syncthreads();
        const float* sx = sxb[ch & 1];
        const float* sw = swb[ch & 1];
        if (ch < NCH - 1) {
#pragma unroll
            for (int kk = 0; kk < 32; ++kk) PROJ_K(sx, sw, kk)
        } else {
#pragma unroll
            for (int kk = 0; kk < KHALF - 32 * (NCH - 1); ++kk) PROJ_K(sx, sw, kk)
        }
        __syncthreads();
        issue_chunk(ch + 2);
        cp_commit();
    }
#undef PROJ_K

    // ---- epilogue: unpack, bias (half 0 only), 0.5-scale i/f/o, permuted store ----
    float va[16], vb[16];
#pragma unroll
    for (int m = 0; m < 8; ++m) { unpack2(accA[m], va[2*m], va[2*m+1]);
                                  unpack2(accB[m], vb[2*m], vb[2*m+1]); }
    if (half == 0) {
#pragma unroll
        for (int g = 0; g < 16; ++g) {
            const float b = __ldg(&bih[g]) + __ldg(&bhh[g]);
            va[g] += b; vb[g] += b;
        }
    }
#pragma unroll
    for (int g = 0; g < 16; ++g) {
        const float sc = (g >= 8 && g < 12) ? 1.0f : 0.5f;  // g-gate unscaled
        va[g] *= sc; vb[g] *= sc;
    }

    float* dst = (half == 0) ? g_xp0 : g_xp1;
    const size_t ra = (row0 + 2 * tid) * NG;
#pragma unroll
    for (int j = 0; j < 4; ++j) {
        *reinterpret_cast<float4*>(&dst[ra + j * 4]) =
            make_float4(va[j], va[4 + j], va[8 + j], va[12 + j]);
        *reinterpret_cast<float4*>(&dst[ra + NG + j * 4]) =
            make_float4(vb[j], vb[4 + j], vb[8 + j], vb[12 + j]);
    }
}

// =====================================================================
// Kernel 2: forward LSTM recurrence. 16 blocks x 32 threads, 4 lanes/batch.
// tanh.approx everywhere; sigmoids via 0.5-folded tanh (scaling done in proj
// epilogue + W_hh load). Ring prefetch depth 8 hides L2 latency.
// =====================================================================
__global__ __launch_bounds__(32) void lstm_fwd_kernel(const float* __restrict__ Whh) {
    const int lane = threadIdx.x;
    const int j  = lane & 3;
    const int bi = blockIdx.x * 8 + (lane >> 2);

    float wi[4], wf[4], wg[4], wo[4];
#pragma unroll
    for (int k = 0; k < 4; ++k) {
        wi[k] = 0.5f * __ldg(&Whh[(0  + j) * 4 + k]);
        wf[k] = 0.5f * __ldg(&Whh[(4  + j) * 4 + k]);
        wg[k] =        __ldg(&Whh[(8  + j) * 4 + k]);
        wo[k] = 0.5f * __ldg(&Whh[(12 + j) * 4 + k]);
    }

    const float4* xp0 = reinterpret_cast<const float4*>(g_xp0) + (size_t)bi * TSEQ * 4 + j;
    const float4* xp1 = reinterpret_cast<const float4*>(g_xp1) + (size_t)bi * TSEQ * 4 + j;

    float4 A0[8], A1[8];
#pragma unroll
    for (int i = 0; i < 8; ++i) { A0[i] = xp0[(size_t)i * 4]; A1[i] = xp1[(size_t)i * 4]; }

    float h0 = 0.f, h1 = 0.f, h2 = 0.f, h3 = 0.f, c = 0.f, hj = 0.f;

#pragma unroll 8
    for (int t = 0; t < TSEQ; ++t) {
        const int s = t & 7;
        const float4 q0 = A0[s];
        const float4 q1 = A1[s];
        if (t + 8 < TSEQ) {
            A0[s] = xp0[(size_t)(t + 8) * 4];
            A1[s] = xp1[(size_t)(t + 8) * 4];
        }
        const float px = q0.x + q1.x;
        const float py = q0.y + q1.y;
        const float pz = q0.z + q1.z;
        const float pw = q0.w + q1.w;

        // gate preacts, depth-balanced trees
        float ip = fmaf(wi[1], h1, fmaf(wi[0], h0, px)) + fmaf(wi[3], h3, wi[2] * h2);
        float fp = fmaf(wf[1], h1, fmaf(wf[0], h0, py)) + fmaf(wf[3], h3, wf[2] * h2);
        float gp = fmaf(wg[1], h1, fmaf(wg[0], h0, pz)) + fmaf(wg[3], h3, wg[2] * h2);
        float op = fmaf(wo[1], h1, fmaf(wo[0], h0, pw)) + fmaf(wo[3], h3, wo[2] * h2);

        const float ti = tanha(ip);   // sigma(i) = 0.5 ti + 0.5 (scaling folded)
        const float tf = tanha(fp);
        const float tg = tanha(gp);   // g gate (true tanh)
        const float to = tanha(op);

        // c = sigma(f)*c + sigma(i)*g = 0.5*(fma(tf,c,c) + fma(ti,tg,tg))
        const float u = fmaf(tf, c, c);
        const float v = fmaf(ti, tg, tg);
        c = 0.5f * (u + v);

        const float tc = tanha(c);
        const float oh = fmaf(to, 0.5f, 0.5f);   // sigma(o), parallel to tanh(c)
        hj = tc * oh;

        h0 = __shfl_sync(0xffffffffu, hj, 0, 4);
        h1 = __shfl_sync(0xffffffffu, hj, 1, 4);
        h2 = __shfl_sync(0xffffffffu, hj, 2, 4);
        h3 = __shfl_sync(0xffffffffu, hj, 3, 4);
    }

    g_hf[bi * 4 + j] = hj;
}

// =====================================================================
// Kernel 3: backward direction = ONE cell on x[:,T-1] (h0=c0=0 => W_hh_b
// unused, f-gate unused) + output head. Accurate activations (off critical path).
// =====================================================================
__global__ __launch_bounds__(128) void tail_kernel(const float* __restrict__ x,
                                                   const float* __restrict__ Wihb,
                                                   const float* __restrict__ bihb,
                                                   const float* __restrict__ bhhb,
                                                   const float* __restrict__ Wout,
                                                   const float* __restrict__ bout,
                                                   float* __restrict__ out) {
    const int b = blockIdx.x;
    const int tid = threadIdx.x;
    const int w = tid >> 5;
    const int l = tid & 31;

    __shared__ float sg[16];

    const float* xr = x + ((size_t)b * TSEQ + (TSEQ - 1)) * KIN;

    float a0 = 0.f, a1 = 0.f, a2 = 0.f, a3 = 0.f;
    for (int k = l; k < KIN; k += 32) {
        float xv = __ldg(&xr[k]);
        a0 = fmaf(xv, __ldg(&Wihb[(size_t)(4 * w + 0) * KIN + k]), a0);
        a1 = fmaf(xv, __ldg(&Wihb[(size_t)(4 * w + 1) * KIN + k]), a1);
        a2 = fmaf(xv, __ldg(&Wihb[(size_t)(4 * w + 2) * KIN + k]), a2);
        a3 = fmaf(xv, __ldg(&Wihb[(size_t)(4 * w + 3) * KIN + k]), a3);
    }
#pragma unroll
    for (int s = 16; s > 0; s >>= 1) {
        a0 += __shfl_xor_sync(0xffffffffu, a0, s);
        a1 += __shfl_xor_sync(0xffffffffu, a1, s);
        a2 += __shfl_xor_sync(0xffffffffu, a2, s);
        a3 += __shfl_xor_sync(0xffffffffu, a3, s);
    }
    if (l == 0) {
        sg[4 * w + 0] = a0;
        sg[4 * w + 1] = a1;
        sg[4 * w + 2] = a2;
        sg[4 * w + 3] = a3;
    }
    __syncthreads();

    if (tid == 0) {
        float hb[4], hf[4];
#pragma unroll
        for (int jj = 0; jj < 4; ++jj) {
            float ip = sg[jj]      + __ldg(&bihb[jj])      + __ldg(&bhhb[jj]);
            float gp = sg[8 + jj]  + __ldg(&bihb[8 + jj])  + __ldg(&bhhb[8 + jj]);
            float op = sg[12 + jj] + __ldg(&bihb[12 + jj]) + __ldg(&bhhb[12 + jj]);
            float iv = sigmoid_acc(ip);
            float gv = tanh_acc(gp);
            float ov = sigmoid_acc(op);
            float cc = iv * gv;                 // c0 = 0 => f-gate drops out
            hb[jj] = ov * tanh_acc(cc);
            hf[jj] = g_hf[b * 4 + jj];
        }
#pragma unroll
        for (int o2 = 0; o2 < 2; ++o2) {
            float s = __ldg(&bout[o2]);
#pragma unroll
            for (int jj = 0; jj < 4; ++jj) {
                s = fmaf(__ldg(&Wout[o2 * 8 + jj]),     hf[jj], s);
                s = fmaf(__ldg(&Wout[o2 * 8 + 4 + jj]), hb[jj], s);
            }
            out[b * 2 + o2] = s;
        }
    }
}

// =====================================================================
extern "C" void kernel_launch(void* const* d_in, const int* in_sizes, int n_in,
                              void* d_out, int out_size) {
    const float* x    = (const float*)d_in[0];
    const float* Wihf = (const float*)d_in[1];
    const float* Whhf = (const float*)d_in[2];
    const float* bihf = (const float*)d_in[3];
    const float* bhhf = (const float*)d_in[4];
    const float* Wihb = (const float*)d_in[5];
    // d_in[6] = W_hh_b: provably unused (backward output only needs step 1 from zero state)
    const float* bihb = (const float*)d_in[7];
    const float* bhhb = (const float*)d_in[8];
    const float* Wout = (const float*)d_in[9];
    const float* bout = (const float*)d_in[10];
    float* out = (float*)d_out;

    constexpr int SMEM_BYTES = (2 * 32 * PITCH + 2 * 32 * 16) * 4;  // 70144
    cudaFuncSetAttribute(proj_kernel, cudaFuncAttributeMaxDynamicSharedMemorySize, SMEM_BYTES);

    dim3 pgrid(BATCH * TSEQ / RPB, 2);   // (256, 2)
    proj_kernel<<<pgrid, 128, SMEM_BYTES>>>(x, Wihf, bihf, bhhf);
    lstm_fwd_kernel<<<BATCH / 8, 32>>>(Whhf);
    tail_kernel<<<BATCH, 128>>>(x, Wihb, bihb, bhhb, Wout, bout, out);
}

// round 3
// speedup vs baseline: 1.0247x; 1.0247x over previous
#include <cuda_runtime.h>

// Problem constants
constexpr int BATCH = 128;
constexpr int TSEQ  = 512;
constexpr int KIN   = 906;
constexpr int NG    = 16;      // 4*H gates
constexpr int TPAD  = TSEQ + 4;  // padded stride for lstm prefetch

// Scratch (device globals; zero-initialized; no allocation allowed)
__device__ __align__(16) float g_wT[KIN * NG];            // W_ih_f^T, [k][gate], i/f/o pre-scaled 0.5
__device__ float g_bs[NG];                                 // scaled bias
__device__ __align__(16) float g_xps[4][BATCH * TSEQ * NG]; // K-quarter partials, permuted [row][j][ifgo]
__device__ __align__(16) float g_xpc[BATCH * TPAD * NG];   // combined, padded stride
__device__ float g_hf[BATCH * 4];

// ---------- packed fp32x2 helpers (Blackwell FFMA2) ----------
__device__ __forceinline__ unsigned long long pack2(float x) {
    unsigned long long r;
    asm("mov.b64 %0, {%1, %1};" : "=l"(r) : "f"(x));
    return r;
}
__device__ __forceinline__ unsigned long long fma2(unsigned long long a,
                                                   unsigned long long b,
                                                   unsigned long long c) {
    unsigned long long d;
    asm("fma.rn.f32x2 %0, %1, %2, %3;" : "=l"(d) : "l"(a), "l"(b), "l"(c));
    return d;
}
__device__ __forceinline__ void unpack2(unsigned long long a, float& lo, float& hi) {
    asm("mov.b64 {%0, %1}, %2;" : "=f"(lo), "=f"(hi) : "l"(a));
}

// ---------- activations ----------
__device__ __forceinline__ float tanha(float x) {   // MUFU.TANH
    float r;
    asm("tanh.approx.f32 %0, %1;" : "=f"(r) : "f"(x));
    return r;
}
__device__ __forceinline__ float sigmoid_acc(float x) {
    float e = __expf(-x);
    return __fdividef(1.0f, 1.0f + e);
}
__device__ __forceinline__ float tanh_acc(float x) {
    float e = __expf(2.0f * x);
    return 1.0f - __fdividef(2.0f, 1.0f + e);
}

// =====================================================================
// Kernel 0: prep — transpose W_ih_f to [k][g] with 0.5 folding; scaled bias.
// =====================================================================
__global__ __launch_bounds__(256) void prep_kernel(const float* __restrict__ Wih,
                                                   const float* __restrict__ bih,
                                                   const float* __restrict__ bhh) {
    const int tid = threadIdx.x;
    for (int i = tid; i < KIN * NG; i += 256) {
        const int k = i >> 4;
        const int g = i & 15;
        const float sc = (g >= 8 && g < 12) ? 1.0f : 0.5f;   // g-gate unscaled
        g_wT[i] = sc * __ldg(&Wih[(size_t)g * KIN + k]);
    }
    if (tid < NG) {
        const float sc = (tid >= 8 && tid < 12) ? 1.0f : 0.5f;
        g_bs[tid] = sc * (__ldg(&bih[tid]) + __ldg(&bhh[tid]));
    }
}

// =====================================================================
// Kernel 1: projection, register-direct, no SMEM, no syncs.
// grid (128, 4): blockIdx.y = K-quarter; 128 threads/block, 4 rows/thread.
// Quarters: [0,228) [228,456) [456,684) [684,906)  (all float2-aligned)
// =====================================================================
__global__ __launch_bounds__(128) void proj_kernel(const float* __restrict__ x) {
    const int tid = threadIdx.x;
    const int q = blockIdx.y;
    const int k0 = q * 228;
    const int k1 = (q == 3) ? KIN : (k0 + 228);
    const size_t row0 = (size_t)blockIdx.x * 512 + (size_t)tid * 4;
    const float* xr = x + row0 * KIN;

    unsigned long long acc[4][8];
#pragma unroll
    for (int r = 0; r < 4; ++r)
#pragma unroll
        for (int m = 0; m < 8; ++m) acc[r][m] = 0ull;

    const ulonglong2* wT = reinterpret_cast<const ulonglong2*>(g_wT);

#pragma unroll 2
    for (int kk = k0; kk < k1; kk += 2) {
        // x for 4 rows (this thread's own rows; sequential per thread, L1-friendly)
        float2 xv[4];
#pragma unroll
        for (int r = 0; r < 4; ++r)
            xv[r] = __ldg(reinterpret_cast<const float2*>(xr + (size_t)r * KIN + kk));

        // W vectors for k = kk and kk+1 (broadcast, L1-resident)
        const ulonglong2* wp = wT + (size_t)kk * 4;
#pragma unroll
        for (int kp = 0; kp < 2; ++kp) {
            const ulonglong2 wA = __ldg(wp + kp * 4 + 0);
            const ulonglong2 wB = __ldg(wp + kp * 4 + 1);
            const ulonglong2 wC = __ldg(wp + kp * 4 + 2);
            const ulonglong2 wD = __ldg(wp + kp * 4 + 3);
#pragma unroll
            for (int r = 0; r < 4; ++r) {
                const float xs = kp ? xv[r].y : xv[r].x;
                const unsigned long long xx = pack2(xs);
                acc[r][0] = fma2(xx, wA.x, acc[r][0]);
                acc[r][1] = fma2(xx, wA.y, acc[r][1]);
                acc[r][2] = fma2(xx, wB.x, acc[r][2]);
                acc[r][3] = fma2(xx, wB.y, acc[r][3]);
                acc[r][4] = fma2(xx, wC.x, acc[r][4]);
                acc[r][5] = fma2(xx, wC.y, acc[r][5]);
                acc[r][6] = fma2(xx, wD.x, acc[r][6]);
                acc[r][7] = fma2(xx, wD.y, acc[r][7]);
            }
        }
    }

    // epilogue: unpack, bias on quarter 0, permuted store [j][ifgo]
    float* dst = g_xps[q];
#pragma unroll
    for (int r = 0; r < 4; ++r) {
        float v[16];
#pragma unroll
        for (int m = 0; m < 8; ++m) unpack2(acc[r][m], v[2 * m], v[2 * m + 1]);
        if (q == 0) {
#pragma unroll
            for (int g = 0; g < 16; ++g) v[g] += g_bs[g];
        }
        const size_t base = (row0 + r) * NG;
#pragma unroll
        for (int j = 0; j < 4; ++j)
            *reinterpret_cast<float4*>(&dst[base + j * 4]) =
                make_float4(v[j], v[4 + j], v[8 + j], v[12 + j]);
    }
}

// =====================================================================
// Kernel 2: combine 4 partials -> g_xpc with padded per-batch stride TPAD.
// =====================================================================
__global__ __launch_bounds__(256) void combine_kernel() {
    const size_t idx = (size_t)blockIdx.x * 256 + threadIdx.x;  // float4 index
    const size_t row = idx >> 2;                                 // b*512 + t
    const int e = (int)(idx & 3);
    const size_t b = row >> 9;
    const size_t t = row & 511;

    const float4* p0 = reinterpret_cast<const float4*>(g_xps[0]) + idx;
    const float4* p1 = reinterpret_cast<const float4*>(g_xps[1]) + idx;
    const float4* p2 = reinterpret_cast<const float4*>(g_xps[2]) + idx;
    const float4* p3 = reinterpret_cast<const float4*>(g_xps[3]) + idx;
    float4 a = *p0, s1 = *p1, s2 = *p2, s3 = *p3;
    a.x += s1.x + s2.x + s3.x;
    a.y += s1.y + s2.y + s3.y;
    a.z += s1.z + s2.z + s3.z;
    a.w += s1.w + s2.w + s3.w;

    reinterpret_cast<float4*>(g_xpc)[(b * TPAD + t) * 4 + e] = a;
}

// =====================================================================
// Kernel 3: forward LSTM recurrence — 8 blocks x 32 threads,
// 2 independent batches per lane (latency hiding), ring prefetch depth 4.
// =====================================================================
__global__ __launch_bounds__(32) void lstm_fwd_kernel(const float* __restrict__ Whh) {
    const int lane = threadIdx.x;
    const int j  = lane & 3;
    const int pr = lane >> 2;                 // 0..7
    const int bA = blockIdx.x * 16 + pr;
    const int bB = bA + 8;

    float wi[4], wf[4], wg[4], wo[4];
#pragma unroll
    for (int k = 0; k < 4; ++k) {
        wi[k] = 0.5f * __ldg(&Whh[(0  + j) * 4 + k]);
        wf[k] = 0.5f * __ldg(&Whh[(4  + j) * 4 + k]);
        wg[k] =        __ldg(&Whh[(8  + j) * 4 + k]);
        wo[k] = 0.5f * __ldg(&Whh[(12 + j) * 4 + k]);
    }

    const float4* pA = reinterpret_cast<const float4*>(g_xpc) + (size_t)bA * TPAD * 4 + j;
    const float4* pB = reinterpret_cast<const float4*>(g_xpc) + (size_t)bB * TPAD * 4 + j;

    float4 RA[4], RB[4];
#pragma unroll
    for (int i = 0; i < 4; ++i) { RA[i] = pA[(size_t)i * 4]; RB[i] = pB[(size_t)i * 4]; }

    float a0 = 0.f, a1 = 0.f, a2 = 0.f, a3 = 0.f, cA = 0.f, hA = 0.f;
    float b0 = 0.f, b1 = 0.f, b2 = 0.f, b3 = 0.f, cB = 0.f, hB = 0.f;

#pragma unroll 4
    for (int t = 0; t < TSEQ; ++t) {
        const int s = t & 3;
        const float4 qA = RA[s];
        const float4 qB = RB[s];
        RA[s] = pA[(size_t)(t + 4) * 4];   // pad rows make this safe (zeros, never consumed)
        RB[s] = pB[(size_t)(t + 4) * 4];

        // ---- batch A ----
        float ipA = fmaf(wi[1], a1, fmaf(wi[0], a0, qA.x)) + fmaf(wi[3], a3, wi[2] * a2);
        float fpA = fmaf(wf[1], a1, fmaf(wf[0], a0, qA.y)) + fmaf(wf[3], a3, wf[2] * a2);
        float gpA = fmaf(wg[1], a1, fmaf(wg[0], a0, qA.z)) + fmaf(wg[3], a3, wg[2] * a2);
        float opA = fmaf(wo[1], a1, fmaf(wo[0], a0, qA.w)) + fmaf(wo[3], a3, wo[2] * a2);
        // ---- batch B ----
        float ipB = fmaf(wi[1], b1, fmaf(wi[0], b0, qB.x)) + fmaf(wi[3], b3, wi[2] * b2);
        float fpB = fmaf(wf[1], b1, fmaf(wf[0], b0, qB.y)) + fmaf(wf[3], b3, wf[2] * b2);
        float gpB = fmaf(wg[1], b1, fmaf(wg[0], b0, qB.z)) + fmaf(wg[3], b3, wg[2] * b2);
        float opB = fmaf(wo[1], b1, fmaf(wo[0], b0, qB.w)) + fmaf(wo[3], b3, wo[2] * b2);

        const float tgA = tanha(gpA);
        const float tiA = tanha(ipA);
        const float tfA = tanha(fpA);
        const float toA = tanha(opA);
        const float tgB = tanha(gpB);
        const float tiB = tanha(ipB);
        const float tfB = tanha(fpB);
        const float toB = tanha(opB);

        const float uA = fmaf(tfA, cA, cA);
        const float vA = fmaf(tiA, tgA, tgA);
        cA = 0.5f * (uA + vA);
        const float uB = fmaf(tfB, cB, cB);
        const float vB = fmaf(tiB, tgB, tgB);
        cB = 0.5f * (uB + vB);

        const float tcA = tanha(cA);
        const float ohA = fmaf(toA, 0.5f, 0.5f);
        hA = tcA * ohA;
        const float tcB = tanha(cB);
        const float ohB = fmaf(toB, 0.5f, 0.5f);
        hB = tcB * ohB;

        a0 = __shfl_sync(0xffffffffu, hA, 0, 4);
        a1 = __shfl_sync(0xffffffffu, hA, 1, 4);
        a2 = __shfl_sync(0xffffffffu, hA, 2, 4);
        a3 = __shfl_sync(0xffffffffu, hA, 3, 4);
        b0 = __shfl_sync(0xffffffffu, hB, 0, 4);
        b1 = __shfl_sync(0xffffffffu, hB, 1, 4);
        b2 = __shfl_sync(0xffffffffu, hB, 2, 4);
        b3 = __shfl_sync(0xffffffffu, hB, 3, 4);
    }

    g_hf[bA * 4 + j] = hA;
    g_hf[bB * 4 + j] = hB;
}

// =====================================================================
// Kernel 4: backward direction = ONE cell on x[:,T-1] + output head.
// =====================================================================
__global__ __launch_bounds__(128) void tail_kernel(const float* __restrict__ x,
                                                   const float* __restrict__ Wihb,
                                                   const float* __restrict__ bihb,
                                                   const float* __restrict__ bhhb,
                                                   const float* __restrict__ Wout,
                                                   const float* __restrict__ bout,
                                                   float* __restrict__ out) {
    const int b = blockIdx.x;
    const int tid = threadIdx.x;
    const int w = tid >> 5;
    const int l = tid & 31;

    __shared__ float sg[16];

    const float* xr = x + ((size_t)b * TSEQ + (TSEQ - 1)) * KIN;

    float a0 = 0.f, a1 = 0.f, a2 = 0.f, a3 = 0.f;
    for (int k = l; k < KIN; k += 32) {
        float xv = __ldg(&xr[k]);
        a0 = fmaf(xv, __ldg(&Wihb[(size_t)(4 * w + 0) * KIN + k]), a0);
        a1 = fmaf(xv, __ldg(&Wihb[(size_t)(4 * w + 1) * KIN + k]), a1);
        a2 = fmaf(xv, __ldg(&Wihb[(size_t)(4 * w + 2) * KIN + k]), a2);
        a3 = fmaf(xv, __ldg(&Wihb[(size_t)(4 * w + 3) * KIN + k]), a3);
    }
#pragma unroll
    for (int s = 16; s > 0; s >>= 1) {
        a0 += __shfl_xor_sync(0xffffffffu, a0, s);
        a1 += __shfl_xor_sync(0xffffffffu, a1, s);
        a2 += __shfl_xor_sync(0xffffffffu, a2, s);
        a3 += __shfl_xor_sync(0xffffffffu, a3, s);
    }
    if (l == 0) {
        sg[4 * w + 0] = a0;
        sg[4 * w + 1] = a1;
        sg[4 * w + 2] = a2;
        sg[4 * w + 3] = a3;
    }
    __syncthreads();

    if (tid == 0) {
        float hb[4], hf[4];
#pragma unroll
        for (int jj = 0; jj < 4; ++jj) {
            float ip = sg[jj]      + __ldg(&bihb[jj])      + __ldg(&bhhb[jj]);
            float gp = sg[8 + jj]  + __ldg(&bihb[8 + jj])  + __ldg(&bhhb[8 + jj]);
            float op = sg[12 + jj] + __ldg(&bihb[12 + jj]) + __ldg(&bhhb[12 + jj]);
            float iv = sigmoid_acc(ip);
            float gv = tanh_acc(gp);
            float ov = sigmoid_acc(op);
            float cc = iv * gv;                 // c0 = 0 => f-gate drops out
            hb[jj] = ov * tanh_acc(cc);
            hf[jj] = g_hf[b * 4 + jj];
        }
#pragma unroll
        for (int o2 = 0; o2 < 2; ++o2) {
            float s = __ldg(&bout[o2]);
#pragma unroll
            for (int jj = 0; jj < 4; ++jj) {
                s = fmaf(__ldg(&Wout[o2 * 8 + jj]),     hf[jj], s);
                s = fmaf(__ldg(&Wout[o2 * 8 + 4 + jj]), hb[jj], s);
            }
            out[b * 2 + o2] = s;
        }
    }
}

// =====================================================================
extern "C" void kernel_launch(void* const* d_in, const int* in_sizes, int n_in,
                              void* d_out, int out_size) {
    const float* x    = (const float*)d_in[0];
    const float* Wihf = (const float*)d_in[1];
    const float* Whhf = (const float*)d_in[2];
    const float* bihf = (const float*)d_in[3];
    const float* bhhf = (const float*)d_in[4];
    const float* Wihb = (const float*)d_in[5];
    // d_in[6] = W_hh_b: provably unused (backward output only needs step 1 from zero state)
    const float* bihb = (const float*)d_in[7];
    const float* bhhb = (const float*)d_in[8];
    const float* Wout = (const float*)d_in[9];
    const float* bout = (const float*)d_in[10];
    float* out = (float*)d_out;

    prep_kernel<<<1, 256>>>(Wihf, bihf, bhhf);
    dim3 pgrid(BATCH * TSEQ / 512, 4);   // (128, 4)
    proj_kernel<<<pgrid, 128>>>(x);
    combine_kernel<<<(BATCH * TSEQ * NG / 4) / 256, 256>>>();
    lstm_fwd_kernel<<<BATCH / 16, 32>>>(Whhf);
    tail_kernel<<<BATCH, 128>>>(x, Wihb, bihb, bhhb, Wout, bout, out);
}

// round 4
// speedup vs baseline: 1.0603x; 1.0347x over previous
#include <cuda_runtime.h>

// Problem constants
constexpr int BATCH = 128;
constexpr int TSEQ  = 512;
constexpr int KIN   = 906;
constexpr int NG    = 16;       // 4*H gates
constexpr int KHALF = 453;      // K split
constexpr int NCHK  = 15;       // 14*32 + 5
constexpr int PROWS = 256;      // rows per proj block
constexpr int PPITCH = 258;     // k-major x tile pitch (even -> LDS.64 aligned)

// Scratch (device globals; no allocation allowed)
__device__ __align__(16) float g_xph[2][BATCH * TSEQ * NG];  // K-half partials, [t][b][j][ifgo], i/f/o pre-scaled 0.5
__device__ __align__(16) float g_xpt[BATCH * TSEQ * NG];     // combined, [t][b][j][ifgo]
__device__ float g_hf[BATCH * 4];

// ---------- packed fp32x2 helpers (Blackwell FFMA2) ----------
__device__ __forceinline__ unsigned long long pack2(float x) {
    unsigned long long r;
    asm("mov.b64 %0, {%1, %1};" : "=l"(r) : "f"(x));
    return r;
}
__device__ __forceinline__ unsigned long long fma2(unsigned long long a,
                                                   unsigned long long b,
                                                   unsigned long long c) {
    unsigned long long d;
    asm("fma.rn.f32x2 %0, %1, %2, %3;" : "=l"(d) : "l"(a), "l"(b), "l"(c));
    return d;
}
__device__ __forceinline__ void unpack2(unsigned long long a, float& lo, float& hi) {
    asm("mov.b64 {%0, %1}, %2;" : "=f"(lo), "=f"(hi) : "l"(a));
}

// ---------- activations ----------
__device__ __forceinline__ float tanha(float x) {
    float r;
    asm("tanh.approx.f32 %0, %1;" : "=f"(r) : "f"(x));
    return r;
}
__device__ __forceinline__ float sigmoid_acc(float x) {
    float e = __expf(-x);
    return __fdividef(1.0f, 1.0f + e);
}
__device__ __forceinline__ float tanh_acc(float x) {
    float e = __expf(2.0f * x);
    return 1.0f - __fdividef(2.0f, 1.0f + e);
}

// ---------- cp.async 16B ----------
__device__ __forceinline__ void cp16(void* dst, const void* src) {
    unsigned d = (unsigned)__cvta_generic_to_shared(dst);
    asm volatile("cp.async.cg.shared.global [%0], [%1], 16;" :: "r"(d), "l"(src));
}

// =====================================================================
// Kernel 1: projection. grid (256, 2); 128 threads; R=2 rows/thread.
// Coalesced LDG->STS staging into k-major tile; W 0.5-folded at STS.
// Output partials in [t][b][j][ifgo] layout.
// =====================================================================
__global__ __launch_bounds__(128) void proj_kernel(const float* __restrict__ x,
                                                   const float* __restrict__ Wih,
                                                   const float* __restrict__ bih,
                                                   const float* __restrict__ bhh) {
    extern __shared__ float smem[];
    float* const sxT[2] = { smem, smem + 32 * PPITCH };
    float* const swb[2] = { smem + 2 * 32 * PPITCH, smem + 2 * 32 * PPITCH + 512 };

    const int tid  = threadIdx.x;
    const int lane = tid & 31;
    const int wid  = tid >> 5;
    const int half = blockIdx.y;
    const int kb   = half * KHALF;
    const size_t row0 = (size_t)blockIdx.x * PROWS;

    unsigned long long accA[8], accB[8];
#pragma unroll
    for (int m = 0; m < 8; ++m) { accA[m] = 0ull; accB[m] = 0ull; }

    float xreg[64];
    float wreg[4];

    auto ldg_chunk = [&](int ch) {
        const int k = kb + ch * 32 + lane;
        const bool ok = k < kb + KHALF;
        const float* xp = x + row0 * KIN + k;
#pragma unroll
        for (int i = 0; i < 64; ++i) {
            const int r = wid + 4 * i;
            xreg[i] = ok ? __ldg(xp + (size_t)r * KIN) : 0.0f;
        }
#pragma unroll
        for (int jj = 0; jj < 4; ++jj) {
            const int g = wid + 4 * jj;
            const float sc = (g >= 8 && g < 12) ? 1.0f : 0.5f;  // sigmoid fold
            wreg[jj] = ok ? sc * __ldg(Wih + (size_t)g * KIN + k) : 0.0f;
        }
    };
    auto sts_chunk = [&](float* sx, float* sw) {
#pragma unroll
        for (int i = 0; i < 64; ++i) sx[lane * PPITCH + wid + 4 * i] = xreg[i];
#pragma unroll
        for (int jj = 0; jj < 4; ++jj) sw[lane * 16 + wid + 4 * jj] = wreg[jj];
    };

#define PROJ_K(SX, SW, KK)                                                     \
    {                                                                          \
        const float2 xv = *(const float2*)((SX) + (KK) * PPITCH + 2 * tid);    \
        const unsigned long long xa = pack2(xv.x);                             \
        const unsigned long long xb = pack2(xv.y);                             \
        const ulonglong2* wr = (const ulonglong2*)((SW) + (KK) * 16);          \
        ulonglong2 w0 = wr[0], w1 = wr[1];                                     \
        accA[0] = fma2(xa, w0.x, accA[0]);  accB[0] = fma2(xb, w0.x, accB[0]); \
        accA[1] = fma2(xa, w0.y, accA[1]);  accB[1] = fma2(xb, w0.y, accB[1]); \
        accA[2] = fma2(xa, w1.x, accA[2]);  accB[2] = fma2(xb, w1.x, accB[2]); \
        accA[3] = fma2(xa, w1.y, accA[3]);  accB[3] = fma2(xb, w1.y, accB[3]); \
        ulonglong2 w2 = wr[2], w3 = wr[3];                                     \
        accA[4] = fma2(xa, w2.x, accA[4]);  accB[4] = fma2(xb, w2.x, accB[4]); \
        accA[5] = fma2(xa, w2.y, accA[5]);  accB[5] = fma2(xb, w2.y, accB[5]); \
        accA[6] = fma2(xa, w3.x, accA[6]);  accB[6] = fma2(xb, w3.x, accB[6]); \
        accA[7] = fma2(xa, w3.y, accA[7]);  accB[7] = fma2(xb, w3.y, accB[7]); \
    }

    ldg_chunk(0);
    sts_chunk(sxT[0], swb[0]);
    __syncthreads();

    for (int ch = 0; ch < NCHK; ++ch) {
        if (ch + 1 < NCHK) ldg_chunk(ch + 1);
        const float* sx = sxT[ch & 1];
        const float* sw = swb[ch & 1];
        if (ch < NCHK - 1) {
#pragma unroll
            for (int kk = 0; kk < 32; ++kk) PROJ_K(sx, sw, kk)
        } else {
#pragma unroll
            for (int kk = 0; kk < KHALF - 32 * (NCHK - 1); ++kk) PROJ_K(sx, sw, kk)
        }
        if (ch + 1 < NCHK) sts_chunk(sxT[(ch + 1) & 1], swb[(ch + 1) & 1]);
        __syncthreads();
    }
#undef PROJ_K

    // epilogue: unpack, bias (half 0, scaled), store [t][b][j][ifgo]
    float va[16], vb[16];
#pragma unroll
    for (int m = 0; m < 8; ++m) { unpack2(accA[m], va[2*m], va[2*m+1]);
                                  unpack2(accB[m], vb[2*m], vb[2*m+1]); }
    if (half == 0) {
#pragma unroll
        for (int g = 0; g < 16; ++g) {
            const float sc = (g >= 8 && g < 12) ? 1.0f : 0.5f;
            const float b = sc * (__ldg(&bih[g]) + __ldg(&bhh[g]));
            va[g] += b; vb[g] += b;
        }
    }

    float4* dst = reinterpret_cast<float4*>(g_xph[half]);
    const size_t rA = row0 + 2 * tid;
    const size_t tA = rA & 511, bA = rA >> 9;
    const size_t tB = (rA + 1) & 511, bB = (rA + 1) >> 9;
#pragma unroll
    for (int j = 0; j < 4; ++j) {
        dst[(tA * 128 + bA) * 4 + j] = make_float4(va[j], va[4+j], va[8+j], va[12+j]);
        dst[(tB * 128 + bB) * 4 + j] = make_float4(vb[j], vb[4+j], vb[8+j], vb[12+j]);
    }
}

// =====================================================================
// Kernel 2: combine halves (elementwise, fully coalesced).
// =====================================================================
__global__ __launch_bounds__(256) void combine_kernel() {
    const size_t i = (size_t)blockIdx.x * 256 + threadIdx.x;
    const float4 a = reinterpret_cast<const float4*>(g_xph[0])[i];
    const float4 b = reinterpret_cast<const float4*>(g_xph[1])[i];
    reinterpret_cast<float4*>(g_xpt)[i] =
        make_float4(a.x + b.x, a.y + b.y, a.z + b.z, a.w + b.w);
}

// =====================================================================
// Kernel 3: forward LSTM. 8 blocks x 64 threads:
// warp0 = compute (16 batches: dual group, 4 lanes/batch),
// warp1 = copy (cp.async stages of 16 steps into SMEM, double-buffered).
// =====================================================================
__global__ __launch_bounds__(64) void lstm_fwd_kernel(const float* __restrict__ Whh) {
    __shared__ __align__(16) float sx[2][16][16][16];  // [buf][step][b][16]

    const int tid = threadIdx.x;
    const int blk_b0 = blockIdx.x * 16;

    if (tid >= 32) {
        // ---------------- copy warp ----------------
        const int l  = tid & 31;
        const int bb = l & 15;
        const int f0 = (l >> 4) * 8;   // float offset: 0 or 8 (covers 2 float4s)
        auto fill = [&](int s) {
            const int t0 = s * 16;
            const int p = s & 1;
#pragma unroll
            for (int tt = 0; tt < 16; ++tt) {
                const float* src = g_xpt + (((size_t)(t0 + tt) * 128) + blk_b0 + bb) * 16 + f0;
                cp16(&sx[p][tt][bb][f0], src);
                cp16(&sx[p][tt][bb][f0 + 4], src + 4);
            }
        };
        fill(0);
        asm volatile("cp.async.commit_group;");
        asm volatile("cp.async.wait_group 0;" ::: "memory");
        __syncthreads();
        for (int s = 0; s < 32; ++s) {
            if (s + 1 < 32) {
                fill(s + 1);
                asm volatile("cp.async.commit_group;");
                asm volatile("cp.async.wait_group 0;" ::: "memory");
            }
            __syncthreads();
        }
    } else {
        // ---------------- compute warp ----------------
        const int j  = tid & 3;
        const int pr = tid >> 2;
        const int bA = pr, bB = pr + 8;

        // weights: 0.25 = 0.5(sigmoid fold) * 0.5(h2 fold); g-gate 0.5 (h2 fold only)
        float wi[4], wf[4], wg[4], wo[4];
#pragma unroll
        for (int k = 0; k < 4; ++k) {
            wi[k] = 0.25f * __ldg(&Whh[(0  + j) * 4 + k]);
            wf[k] = 0.25f * __ldg(&Whh[(4  + j) * 4 + k]);
            wg[k] = 0.50f * __ldg(&Whh[(8  + j) * 4 + k]);
            wo[k] = 0.25f * __ldg(&Whh[(12 + j) * 4 + k]);
        }

        float a0 = 0.f, a1 = 0.f, a2 = 0.f, a3 = 0.f, cA = 0.f, hA2 = 0.f;
        float e0 = 0.f, e1 = 0.f, e2 = 0.f, e3 = 0.f, cB = 0.f, hB2 = 0.f;

        __syncthreads();   // matches copy prologue sync

        for (int s = 0; s < 32; ++s) {
            const float (*buf)[16][16] = sx[s & 1];
            float4 curA = *reinterpret_cast<const float4*>(&buf[0][bA][4 * j]);
            float4 curB = *reinterpret_cast<const float4*>(&buf[0][bB][4 * j]);
#pragma unroll
            for (int tt = 0; tt < 16; ++tt) {
                float4 nA, nB;
                if (tt < 15) {
                    nA = *reinterpret_cast<const float4*>(&buf[tt + 1][bA][4 * j]);
                    nB = *reinterpret_cast<const float4*>(&buf[tt + 1][bB][4 * j]);
                }

                float ipA = fmaf(wi[1], a1, fmaf(wi[0], a0, curA.x)) + fmaf(wi[3], a3, wi[2] * a2);
                float fpA = fmaf(wf[1], a1, fmaf(wf[0], a0, curA.y)) + fmaf(wf[3], a3, wf[2] * a2);
                float gpA = fmaf(wg[1], a1, fmaf(wg[0], a0, curA.z)) + fmaf(wg[3], a3, wg[2] * a2);
                float opA = fmaf(wo[1], a1, fmaf(wo[0], a0, curA.w)) + fmaf(wo[3], a3, wo[2] * a2);
                float ipB = fmaf(wi[1], e1, fmaf(wi[0], e0, curB.x)) + fmaf(wi[3], e3, wi[2] * e2);
                float fpB = fmaf(wf[1], e1, fmaf(wf[0], e0, curB.y)) + fmaf(wf[3], e3, wf[2] * e2);
                float gpB = fmaf(wg[1], e1, fmaf(wg[0], e0, curB.z)) + fmaf(wg[3], e3, wg[2] * e2);
                float opB = fmaf(wo[1], e1, fmaf(wo[0], e0, curB.w)) + fmaf(wo[3], e3, wo[2] * e2);

                const float tiA = tanha(ipA), tfA = tanha(fpA), tgA = tanha(gpA), toA = tanha(opA);
                const float tiB = tanha(ipB), tfB = tanha(fpB), tgB = tanha(gpB), toB = tanha(opB);

                cA = 0.5f * (fmaf(tfA, cA, cA) + fmaf(tiA, tgA, tgA));
                cB = 0.5f * (fmaf(tfB, cB, cB) + fmaf(tiB, tgB, tgB));

                const float tcA = tanha(cA);
                const float tcB = tanha(cB);
                hA2 = fmaf(toA, tcA, tcA);   // = 2 * h
                hB2 = fmaf(toB, tcB, tcB);

                a0 = __shfl_sync(0xffffffffu, hA2, 0, 4);
                a1 = __shfl_sync(0xffffffffu, hA2, 1, 4);
                a2 = __shfl_sync(0xffffffffu, hA2, 2, 4);
                a3 = __shfl_sync(0xffffffffu, hA2, 3, 4);
                e0 = __shfl_sync(0xffffffffu, hB2, 0, 4);
                e1 = __shfl_sync(0xffffffffu, hB2, 1, 4);
                e2 = __shfl_sync(0xffffffffu, hB2, 2, 4);
                e3 = __shfl_sync(0xffffffffu, hB2, 3, 4);

                curA = nA; curB = nB;
            }
            __syncthreads();
        }

        g_hf[(blk_b0 + bA) * 4 + j] = 0.5f * hA2;
        g_hf[(blk_b0 + bB) * 4 + j] = 0.5f * hB2;
    }
}

// =====================================================================
// Kernel 4: backward direction = ONE cell on x[:,T-1] + output head.
// =====================================================================
__global__ __launch_bounds__(128) void tail_kernel(const float* __restrict__ x,
                                                   const float* __restrict__ Wihb,
                                                   const float* __restrict__ bihb,
                                                   const float* __restrict__ bhhb,
                                                   const float* __restrict__ Wout,
                                                   const float* __restrict__ bout,
                                                   float* __restrict__ out) {
    const int b = blockIdx.x;
    const int tid = threadIdx.x;
    const int w = tid >> 5;
    const int l = tid & 31;

    __shared__ float sg[16];

    const float* xr = x + ((size_t)b * TSEQ + (TSEQ - 1)) * KIN;

    float a0 = 0.f, a1 = 0.f, a2 = 0.f, a3 = 0.f;
    for (int k = l; k < KIN; k += 32) {
        float xv = __ldg(&xr[k]);
        a0 = fmaf(xv, __ldg(&Wihb[(size_t)(4 * w + 0) * KIN + k]), a0);
        a1 = fmaf(xv, __ldg(&Wihb[(size_t)(4 * w + 1) * KIN + k]), a1);
        a2 = fmaf(xv, __ldg(&Wihb[(size_t)(4 * w + 2) * KIN + k]), a2);
        a3 = fmaf(xv, __ldg(&Wihb[(size_t)(4 * w + 3) * KIN + k]), a3);
    }
#pragma unroll
    for (int s = 16; s > 0; s >>= 1) {
        a0 += __shfl_xor_sync(0xffffffffu, a0, s);
        a1 += __shfl_xor_sync(0xffffffffu, a1, s);
        a2 += __shfl_xor_sync(0xffffffffu, a2, s);
        a3 += __shfl_xor_sync(0xffffffffu, a3, s);
    }
    if (l == 0) {
        sg[4 * w + 0] = a0;
        sg[4 * w + 1] = a1;
        sg[4 * w + 2] = a2;
        sg[4 * w + 3] = a3;
    }
    __syncthreads();

    if (tid == 0) {
        float hb[4], hf[4];
#pragma unroll
        for (int jj = 0; jj < 4; ++jj) {
            float ip = sg[jj]      + __ldg(&bihb[jj])      + __ldg(&bhhb[jj]);
            float gp = sg[8 + jj]  + __ldg(&bihb[8 + jj])  + __ldg(&bhhb[8 + jj]);
            float op = sg[12 + jj] + __ldg(&bihb[12 + jj]) + __ldg(&bhhb[12 + jj]);
            float iv = sigmoid_acc(ip);
            float gv = tanh_acc(gp);
            float ov = sigmoid_acc(op);
            float cc = iv * gv;                 // c0 = 0 => f-gate drops out
            hb[jj] = ov * tanh_acc(cc);
            hf[jj] = g_hf[b * 4 + jj];
        }
#pragma unroll
        for (int o2 = 0; o2 < 2; ++o2) {
            float s = __ldg(&bout[o2]);
#pragma unroll
            for (int jj = 0; jj < 4; ++jj) {
                s = fmaf(__ldg(&Wout[o2 * 8 + jj]),     hf[jj], s);
                s = fmaf(__ldg(&Wout[o2 * 8 + 4 + jj]), hb[jj], s);
            }
            out[b * 2 + o2] = s;
        }
    }
}

// =====================================================================
extern "C" void kernel_launch(void* const* d_in, const int* in_sizes, int n_in,
                              void* d_out, int out_size) {
    const float* x    = (const float*)d_in[0];
    const float* Wihf = (const float*)d_in[1];
    const float* Whhf = (const float*)d_in[2];
    const float* bihf = (const float*)d_in[3];
    const float* bhhf = (const float*)d_in[4];
    const float* Wihb = (const float*)d_in[5];
    // d_in[6] = W_hh_b: provably unused (backward output only needs step 1 from zero state)
    const float* bihb = (const float*)d_in[7];
    const float* bhhb = (const float*)d_in[8];
    const float* Wout = (const float*)d_in[9];
    const float* bout = (const float*)d_in[10];
    float* out = (float*)d_out;

    constexpr int PROJ_SMEM = (2 * 32 * PPITCH + 2 * 512) * 4;  // 70144 B
    static bool attr_set = false;
    if (!attr_set) {
        cudaFuncSetAttribute(proj_kernel, cudaFuncAttributeMaxDynamicSharedMemorySize, PROJ_SMEM);
        attr_set = true;
    }

    dim3 pgrid(BATCH * TSEQ / PROWS, 2);   // (256, 2)
    proj_kernel<<<pgrid, 128, PROJ_SMEM>>>(x, Wihf, bihf, bhhf);
    combine_kernel<<<BATCH * TSEQ * NG / 4 / 256, 256>>>();
    lstm_fwd_kernel<<<8, 64>>>(Whhf);
    tail_kernel<<<BATCH, 128>>>(x, Wihb, bihb, bhhb, Wout, bout, out);
}

// round 5
// speedup vs baseline: 1.7040x; 1.6070x over previous
#include <cuda_runtime.h>

// Problem constants
constexpr int BATCH = 128;
constexpr int TSEQ  = 512;
constexpr int KIN   = 906;
constexpr int NG    = 16;       // 4*H gates
constexpr int KHALF = 453;      // K split
constexpr int CK    = 16;       // k per chunk
constexpr int NCHK  = 29;       // 28*16 + 5
constexpr int PROWS = 256;      // rows per proj block
constexpr int PITCH = 258;      // k-major tile pitch (floats)

// Scratch (device globals; no allocation allowed)
// K-half partials, layout [t][b][j][ifgo]; i/f/o pre-scaled 0.5 (sigmoid fold)
__device__ __align__(16) float g_xph[2][BATCH * TSEQ * NG];
__device__ float g_hf[BATCH * 4];

// ---------- packed fp32x2 helpers (Blackwell FFMA2) ----------
__device__ __forceinline__ unsigned long long pack2(float x) {
    unsigned long long r;
    asm("mov.b64 %0, {%1, %1};" : "=l"(r) : "f"(x));
    return r;
}
__device__ __forceinline__ unsigned long long fma2(unsigned long long a,
                                                   unsigned long long b,
                                                   unsigned long long c) {
    unsigned long long d;
    asm("fma.rn.f32x2 %0, %1, %2, %3;" : "=l"(d) : "l"(a), "l"(b), "l"(c));
    return d;
}
__device__ __forceinline__ void unpack2(unsigned long long a, float& lo, float& hi) {
    asm("mov.b64 {%0, %1}, %2;" : "=f"(lo), "=f"(hi) : "l"(a));
}

// ---------- activations ----------
__device__ __forceinline__ float tanha(float x) {
    float r;
    asm("tanh.approx.f32 %0, %1;" : "=f"(r) : "f"(x));
    return r;
}
__device__ __forceinline__ float sigmoid_acc(float x) {
    float e = __expf(-x);
    return __fdividef(1.0f, 1.0f + e);
}
__device__ __forceinline__ float tanh_acc(float x) {
    float e = __expf(2.0f * x);
    return 1.0f - __fdividef(2.0f, 1.0f + e);
}

// ---------- cp.async 16B ----------
__device__ __forceinline__ void cp16(void* dst, const void* src) {
    unsigned d = (unsigned)__cvta_generic_to_shared(dst);
    asm volatile("cp.async.cg.shared.global [%0], [%1], 16;" :: "r"(d), "l"(src));
}

// =====================================================================
// Kernel 1: projection. grid (256, 2) = 512 blocks; 128 threads; R=2.
// 16-k chunks, k-major x tile (LDS.64 serves both rows), W tile 16x16.
// Conflict-free STS/LDS by construction. Static SMEM = 35 KB.
// =====================================================================
__global__ __launch_bounds__(128) void proj_kernel(const float* __restrict__ x,
                                                   const float* __restrict__ Wih,
                                                   const float* __restrict__ bih,
                                                   const float* __restrict__ bhh) {
    __shared__ __align__(16) float sxT[2][CK * PITCH];  // [buf][k][row]
    __shared__ __align__(16) float sw[2][CK * 16];      // [buf][k][gate]

    const int tid  = threadIdx.x;
    const int lane = tid & 31;
    const int wid  = tid >> 5;
    const int half = blockIdx.y;
    const int kb   = half * KHALF;
    const size_t row0 = (size_t)blockIdx.x * PROWS;

    const int kk_l = lane & 15;     // k within chunk
    const int rs   = lane >> 4;     // row sub (0/1)

    unsigned long long accA[8], accB[8];
#pragma unroll
    for (int m = 0; m < 8; ++m) { accA[m] = 0ull; accB[m] = 0ull; }

    float xreg[32];
    float wreg[2];

    // coalesced LDG of chunk ch into registers
    auto ldg_chunk = [&](int ch) {
        const int kloc = ch * CK + kk_l;
        const bool ok = kloc < KHALF;
        const float* xp = x + (row0 + 64 * wid + rs) * KIN + kb + kloc;
#pragma unroll
        for (int i = 0; i < 32; ++i)
            xreg[i] = ok ? __ldg(xp + (size_t)2 * i * KIN) : 0.0f;
        // W: 256 values, 128 threads x 2
#pragma unroll
        for (int u = 0; u < 2; ++u) {
            const int idx = tid + 128 * u;
            const int kw = idx >> 4, g = idx & 15;
            const int kwl = ch * CK + kw;
            const float sc = (g >= 8 && g < 12) ? 1.0f : 0.5f;
            wreg[u] = (kwl < KHALF) ? sc * __ldg(Wih + (size_t)g * KIN + kb + kwl) : 0.0f;
        }
    };
    auto sts_chunk = [&](int buf) {
        float* sx = sxT[buf];
#pragma unroll
        for (int i = 0; i < 32; ++i)
            sx[kk_l * PITCH + 64 * wid + rs + 2 * i] = xreg[i];
        float* swp = sw[buf];
#pragma unroll
        for (int u = 0; u < 2; ++u) {
            const int idx = tid + 128 * u;
            swp[idx] = wreg[u];    // [k][g] layout: idx = k*16+g
        }
    };

#define PROJ_K(SX, SW, KK)                                                     \
    {                                                                          \
        const float2 xv = *(const float2*)((SX) + (KK) * PITCH + 2 * tid);     \
        const unsigned long long xa = pack2(xv.x);                             \
        const unsigned long long xb = pack2(xv.y);                             \
        const ulonglong2* wr = (const ulonglong2*)((SW) + (KK) * 16);          \
        ulonglong2 w0 = wr[0], w1 = wr[1];                                     \
        accA[0] = fma2(xa, w0.x, accA[0]);  accB[0] = fma2(xb, w0.x, accB[0]); \
        accA[1] = fma2(xa, w0.y, accA[1]);  accB[1] = fma2(xb, w0.y, accB[1]); \
        accA[2] = fma2(xa, w1.x, accA[2]);  accB[2] = fma2(xb, w1.x, accB[2]); \
        accA[3] = fma2(xa, w1.y, accA[3]);  accB[3] = fma2(xb, w1.y, accB[3]); \
        ulonglong2 w2 = wr[2], w3 = wr[3];                                     \
        accA[4] = fma2(xa, w2.x, accA[4]);  accB[4] = fma2(xb, w2.x, accB[4]); \
        accA[5] = fma2(xa, w2.y, accA[5]);  accB[5] = fma2(xb, w2.y, accB[5]); \
        accA[6] = fma2(xa, w3.x, accA[6]);  accB[6] = fma2(xb, w3.x, accB[6]); \
        accA[7] = fma2(xa, w3.y, accA[7]);  accB[7] = fma2(xb, w3.y, accB[7]); \
    }

    ldg_chunk(0);
    sts_chunk(0);
    __syncthreads();

    for (int ch = 0; ch < NCHK; ++ch) {
        if (ch + 1 < NCHK) ldg_chunk(ch + 1);
        const float* sx = sxT[ch & 1];
        const float* swp = sw[ch & 1];
        if (ch < NCHK - 1) {
#pragma unroll
            for (int kk = 0; kk < CK; ++kk) PROJ_K(sx, swp, kk)
        } else {
#pragma unroll
            for (int kk = 0; kk < KHALF - CK * (NCHK - 1); ++kk) PROJ_K(sx, swp, kk)
        }
        if (ch + 1 < NCHK) sts_chunk((ch + 1) & 1);
        __syncthreads();
    }
#undef PROJ_K

    // epilogue: unpack, bias (half 0, scaled), store [t][b][j][ifgo]
    float va[16], vb[16];
#pragma unroll
    for (int m = 0; m < 8; ++m) { unpack2(accA[m], va[2*m], va[2*m+1]);
                                  unpack2(accB[m], vb[2*m], vb[2*m+1]); }
    if (half == 0) {
#pragma unroll
        for (int g = 0; g < 16; ++g) {
            const float sc = (g >= 8 && g < 12) ? 1.0f : 0.5f;
            const float b = sc * (__ldg(&bih[g]) + __ldg(&bhh[g]));
            va[g] += b; vb[g] += b;
        }
    }

    float4* dst = reinterpret_cast<float4*>(g_xph[half]);
    const size_t rA = row0 + 2 * tid;
    const size_t tA = rA & 511, bA = rA >> 9;
    const size_t tB = (rA + 1) & 511, bB = (rA + 1) >> 9;
#pragma unroll
    for (int j = 0; j < 4; ++j) {
        dst[(tA * 128 + bA) * 4 + j] = make_float4(va[j], va[4+j], va[8+j], va[12+j]);
        dst[(tB * 128 + bB) * 4 + j] = make_float4(vb[j], vb[4+j], vb[8+j], vb[12+j]);
    }
}

// =====================================================================
// Kernel 2: forward LSTM, fused K-half combine. 8 blocks x 64 threads:
// warp0 = compute (16 batches, dual stream, 4 lanes/batch),
// warp1 = copy (cp.async, 16-step stages, both halves, double-buffered).
// =====================================================================
__global__ __launch_bounds__(64) void lstm_fwd_kernel(const float* __restrict__ Whh) {
    extern __shared__ float sx[];   // [buf][half][step][b][16] = 2*2*16*16*16 floats (64 KB)
    auto buf_at = [&](int p, int h, int tt, int b) -> float* {
        return sx + (((p * 2 + h) * 16 + tt) * 16 + b) * 16;
    };

    const int tid = threadIdx.x;
    const int blk_b0 = blockIdx.x * 16;

    if (tid >= 32) {
        // ---------------- copy warp ----------------
        const int l  = tid & 31;
        const int bb = l & 15;
        const int f0 = (l >> 4) * 8;
        auto fill = [&](int s) {
            const int t0 = s * 16;
            const int p = s & 1;
#pragma unroll
            for (int h = 0; h < 2; ++h) {
                const float* base = g_xph[h];
#pragma unroll
                for (int tt = 0; tt < 16; ++tt) {
                    const float* src = base + (((size_t)(t0 + tt) * 128) + blk_b0 + bb) * 16 + f0;
                    float* d = buf_at(p, h, tt, bb) + f0;
                    cp16(d, src);
                    cp16(d + 4, src + 4);
                }
            }
        };
        fill(0);
        asm volatile("cp.async.commit_group;");
        asm volatile("cp.async.wait_group 0;" ::: "memory");
        __syncthreads();
        for (int s = 0; s < 32; ++s) {
            if (s + 1 < 32) {
                fill(s + 1);
                asm volatile("cp.async.commit_group;");
                asm volatile("cp.async.wait_group 0;" ::: "memory");
            }
            __syncthreads();
        }
    } else {
        // ---------------- compute warp ----------------
        const int j  = tid & 3;
        const int pr = tid >> 2;
        const int bA = pr, bB = pr + 8;

        // 0.25 = 0.5(sigmoid fold) * 0.5(h2 fold); g-gate 0.5 (h2 fold only)
        float wi[4], wf[4], wg[4], wo[4];
#pragma unroll
        for (int k = 0; k < 4; ++k) {
            wi[k] = 0.25f * __ldg(&Whh[(0  + j) * 4 + k]);
            wf[k] = 0.25f * __ldg(&Whh[(4  + j) * 4 + k]);
            wg[k] = 0.50f * __ldg(&Whh[(8  + j) * 4 + k]);
            wo[k] = 0.25f * __ldg(&Whh[(12 + j) * 4 + k]);
        }

        float a0 = 0.f, a1 = 0.f, a2 = 0.f, a3 = 0.f, cA = 0.f, hA2 = 0.f;
        float e0 = 0.f, e1 = 0.f, e2 = 0.f, e3 = 0.f, cB = 0.f, hB2 = 0.f;

        __syncthreads();   // matches copy prologue sync

        for (int s = 0; s < 32; ++s) {
            const int p = s & 1;
            float4 cA0 = *reinterpret_cast<const float4*>(buf_at(p, 0, 0, bA) + 4 * j);
            float4 cA1 = *reinterpret_cast<const float4*>(buf_at(p, 1, 0, bA) + 4 * j);
            float4 cB0 = *reinterpret_cast<const float4*>(buf_at(p, 0, 0, bB) + 4 * j);
            float4 cB1 = *reinterpret_cast<const float4*>(buf_at(p, 1, 0, bB) + 4 * j);
#pragma unroll
            for (int tt = 0; tt < 16; ++tt) {
                float4 nA0, nA1, nB0, nB1;
                if (tt < 15) {
                    nA0 = *reinterpret_cast<const float4*>(buf_at(p, 0, tt + 1, bA) + 4 * j);
                    nA1 = *reinterpret_cast<const float4*>(buf_at(p, 1, tt + 1, bA) + 4 * j);
                    nB0 = *reinterpret_cast<const float4*>(buf_at(p, 0, tt + 1, bB) + 4 * j);
                    nB1 = *reinterpret_cast<const float4*>(buf_at(p, 1, tt + 1, bB) + 4 * j);
                }

                // two balanced trees; half-1 partial folded into second tree
                float ipA = fmaf(wi[1], a1, fmaf(wi[0], a0, cA0.x)) + fmaf(wi[3], a3, fmaf(wi[2], a2, cA1.x));
                float fpA = fmaf(wf[1], a1, fmaf(wf[0], a0, cA0.y)) + fmaf(wf[3], a3, fmaf(wf[2], a2, cA1.y));
                float gpA = fmaf(wg[1], a1, fmaf(wg[0], a0, cA0.z)) + fmaf(wg[3], a3, fmaf(wg[2], a2, cA1.z));
                float opA = fmaf(wo[1], a1, fmaf(wo[0], a0, cA0.w)) + fmaf(wo[3], a3, fmaf(wo[2], a2, cA1.w));
                float ipB = fmaf(wi[1], e1, fmaf(wi[0], e0, cB0.x)) + fmaf(wi[3], e3, fmaf(wi[2], e2, cB1.x));
                float fpB = fmaf(wf[1], e1, fmaf(wf[0], e0, cB0.y)) + fmaf(wf[3], e3, fmaf(wf[2], e2, cB1.y));
                float gpB = fmaf(wg[1], e1, fmaf(wg[0], e0, cB0.z)) + fmaf(wg[3], e3, fmaf(wg[2], e2, cB1.z));
                float opB = fmaf(wo[1], e1, fmaf(wo[0], e0, cB0.w)) + fmaf(wo[3], e3, fmaf(wo[2], e2, cB1.w));

                const float tiA = tanha(ipA), tfA = tanha(fpA), tgA = tanha(gpA), toA = tanha(opA);
                const float tiB = tanha(ipB), tfB = tanha(fpB), tgB = tanha(gpB), toB = tanha(opB);

                cA = 0.5f * (fmaf(tfA, cA, cA) + fmaf(tiA, tgA, tgA));
                cB = 0.5f * (fmaf(tfB, cB, cB) + fmaf(tiB, tgB, tgB));

                const float tcA = tanha(cA);
                const float tcB = tanha(cB);
                hA2 = fmaf(toA, tcA, tcA);   // = 2*h
                hB2 = fmaf(toB, tcB, tcB);

                a0 = __shfl_sync(0xffffffffu, hA2, 0, 4);
                a1 = __shfl_sync(0xffffffffu, hA2, 1, 4);
                a2 = __shfl_sync(0xffffffffu, hA2, 2, 4);
                a3 = __shfl_sync(0xffffffffu, hA2, 3, 4);
                e0 = __shfl_sync(0xffffffffu, hB2, 0, 4);
                e1 = __shfl_sync(0xffffffffu, hB2, 1, 4);
                e2 = __shfl_sync(0xffffffffu, hB2, 2, 4);
                e3 = __shfl_sync(0xffffffffu, hB2, 3, 4);

                cA0 = nA0; cA1 = nA1; cB0 = nB0; cB1 = nB1;
            }
            __syncthreads();
        }

        g_hf[(blk_b0 + bA) * 4 + j] = 0.5f * hA2;
        g_hf[(blk_b0 + bB) * 4 + j] = 0.5f * hB2;
    }
}

// =====================================================================
// Kernel 3: tail. 128 blocks x 384 threads; warp w reduces one live gate
// row (i: 0-3, g: 8-11, o: 12-15). f-gate provably unused (c0 = 0).
// =====================================================================
__global__ __launch_bounds__(384) void tail_kernel(const float* __restrict__ x,
                                                   const float* __restrict__ Wihb,
                                                   const float* __restrict__ bihb,
                                                   const float* __restrict__ bhhb,
                                                   const float* __restrict__ Wout,
                                                   const float* __restrict__ bout,
                                                   float* __restrict__ out) {
    const int b = blockIdx.x;
    const int tid = threadIdx.x;
    const int w = tid >> 5;
    const int l = tid & 31;
    const int gr = (w < 4) ? w : (w + 4);    // gate row: 0-3, 8-11, 12-15

    __shared__ float sg[12];

    const float* xr = x + ((size_t)b * TSEQ + (TSEQ - 1)) * KIN;
    const float* wr = Wihb + (size_t)gr * KIN;

    float a = 0.f;
    for (int k = l; k < KIN; k += 32)
        a = fmaf(__ldg(&xr[k]), __ldg(&wr[k]), a);
#pragma unroll
    for (int s = 16; s > 0; s >>= 1)
        a += __shfl_xor_sync(0xffffffffu, a, s);
    if (l == 0) sg[w] = a + __ldg(&bihb[gr]) + __ldg(&bhhb[gr]);
    __syncthreads();

    if (tid == 0) {
        float hb[4], hf[4];
#pragma unroll
        for (int jj = 0; jj < 4; ++jj) {
            float iv = sigmoid_acc(sg[jj]);
            float gv = tanh_acc(sg[4 + jj]);
            float ov = sigmoid_acc(sg[8 + jj]);
            float cc = iv * gv;                 // c0 = 0 => f-gate drops out
            hb[jj] = ov * tanh_acc(cc);
            hf[jj] = g_hf[b * 4 + jj];
        }
#pragma unroll
        for (int o2 = 0; o2 < 2; ++o2) {
            float s = __ldg(&bout[o2]);
#pragma unroll
            for (int jj = 0; jj < 4; ++jj) {
                s = fmaf(__ldg(&Wout[o2 * 8 + jj]),     hf[jj], s);
                s = fmaf(__ldg(&Wout[o2 * 8 + 4 + jj]), hb[jj], s);
            }
            out[b * 2 + o2] = s;
        }
    }
}

// =====================================================================
extern "C" void kernel_launch(void* const* d_in, const int* in_sizes, int n_in,
                              void* d_out, int out_size) {
    const float* x    = (const float*)d_in[0];
    const float* Wihf = (const float*)d_in[1];
    const float* Whhf = (const float*)d_in[2];
    const float* bihf = (const float*)d_in[3];
    const float* bhhf = (const float*)d_in[4];
    const float* Wihb = (const float*)d_in[5];
    // d_in[6] = W_hh_b: provably unused (backward output only needs step 1 from zero state)
    const float* bihb = (const float*)d_in[7];
    const float* bhhb = (const float*)d_in[8];
    const float* Wout = (const float*)d_in[9];
    const float* bout = (const float*)d_in[10];
    float* out = (float*)d_out;

    constexpr int LSTM_SMEM = 2 * 2 * 16 * 16 * 16 * 4;   // 65536 B
    static bool attr_set = false;
    if (!attr_set) {
        cudaFuncSetAttribute(lstm_fwd_kernel, cudaFuncAttributeMaxDynamicSharedMemorySize, LSTM_SMEM);
        attr_set = true;
    }

    dim3 pgrid(BATCH * TSEQ / PROWS, 2);   // (256, 2)
    proj_kernel<<<pgrid, 128>>>(x, Wihf, bihf, bhhf);
    lstm_fwd_kernel<<<8, 64, LSTM_SMEM>>>(Whhf);
    tail_kernel<<<BATCH, 384>>>(x, Wihb, bihb, bhhb, Wout, bout, out);
}